// round 10
// baseline (speedup 1.0000x reference)
#include <cuda_runtime.h>
#include <math.h>

#define NHIT 80000
#define TILE 128
#define NBLK 626               // 626 * 128 = 80128
#define NPAD (NBLK * TILE)
#define KOBJ 512
#define KHALF 256
#define HBLK 313               // k_hits blocks (256 thr)
#define NCELL 64               // 8x8 unit cells over [-4,4)

// ---------------- scratch (device globals; zero at load, reset after use) ----------
__device__ float4 g_tmp[NHIT];                 // unsorted hit data
__device__ int    g_cellid[NHIT];
__device__ int    g_ccnt[NCELL];               // hit histogram (must be 0 at entry)
__device__ int    g_cstart[NCELL];
__device__ int    g_coff[NCELL];               // scatter cursors (must be 0 at entry)
__device__ float4 g_hit[NPAD];                 // cell-sorted hits: x, y, q, t_idx bits
__device__ float4 g_alphaK[KOBJ];              // by k: x, y, q, beta
__device__ float4 g_alphaS[KOBJ];              // cell-sorted: x, y, q, k bits
__device__ unsigned long long g_amax[KOBJ];    // packed (beta_bits<<32 | ~idx)
__device__ int    g_cnt[KOBJ];
__device__ float2 g_numden[KOBJ];              // payload num, den
__device__ float  g_att[KOBJ], g_rep[KOBJ];
__device__ float  g_noise_sum, g_noise_cnt, g_cc_sum;
__device__ unsigned g_done_h, g_done_p;

__device__ __forceinline__ float clampb(float b) {
    return fminf(fmaxf(b, 1e-6f), 1.0f - 1e-6f);
}
__device__ __forceinline__ float softclip_f(float x, float c) {
    x = x * (1.0f / c);
    if (x > 1.0f) x = __logf(x + 1.0f);
    return x * c;
}
__device__ __forceinline__ float huber_f(float x, float d) {
    float ax = fabsf(x);
    return ax < d ? x * x : d * d + 2.0f * d * (ax - d);
}
__device__ __forceinline__ float sqapx(float x) {
    float s; asm("sqrt.approx.f32 %0, %1;" : "=f"(s) : "f"(x)); return s;
}
__device__ __forceinline__ int cell_of(float x, float y) {
    int cx = min(max((int)floorf(x) + 4, 0), 7);
    int cy = min(max((int)floorf(y) + 4, 0), 7);
    return cy * 8 + cx;
}

// hinge accumulate: rep += sat(1 - sqrt(d2)) * q
#define REP_ACC(D2, Q, REP)                                         \
    asm("{ .reg .f32 s;\n\t"                                        \
        " sqrt.approx.f32 s, %1;\n\t"                               \
        " sub.rn.sat.f32 s, 0f3F800000, s;\n\t"                     \
        " fma.rn.f32 %0, s, %2, %0;\n\t}"                           \
        : "+f"(REP) : "f"(D2), "f"(Q));

#define PAIR1(H, AX, AY, REP)                                       \
    {                                                               \
        float dx = (H).x - (AX), dy = (H).y - (AY);                 \
        float d2 = fmaf(dx, dx, fmaf(dy, dy, 1e-6f));               \
        REP_ACC(d2, (H).z, REP)                                     \
    }

// ---------------- kernel 1: per-hit pass + histogram + alpha gather/sort ----------
__global__ void __launch_bounds__(256) k_hits(
        const float* __restrict__ pb,  const float* __restrict__ cc,
        const float* __restrict__ pe,  const float* __restrict__ pp,
        const float* __restrict__ pt,  const float* __restrict__ pid,
        const int*   __restrict__ tix, const float* __restrict__ te,
        const float* __restrict__ tp,  const float* __restrict__ tt) {
    __shared__ unsigned s_last;
    int i = blockIdx.x * blockDim.x + threadIdx.x;
    float ns = 0.0f, ncnt = 0.0f, ccs = 0.0f;
    if (i < NHIT) {
        float  braw = pb[i];
        int    t    = tix[i];
        float2 ccv  = ((const float2*)cc)[i];
        float  pev  = pe[i];
        float2 ppv  = ((const float2*)pp)[i];
        float  ptv  = pt[i];
        float  tev  = te[i];
        float2 tpv  = ((const float2*)tp)[i];
        float  ttv  = tt[i];
        float2 pid0 = ((const float2*)pid)[3 * i];
        float2 pid1 = ((const float2*)pid)[3 * i + 1];
        float2 pid2 = ((const float2*)pid)[3 * i + 2];

        float beta = clampb(braw);
        float lg = __logf(__fdividef(1.0f + beta, 1.0f - beta));
        float q = fmaf(0.25f * lg, lg, 0.1f);
        g_tmp[i] = make_float4(ccv.x, ccv.y, q, __int_as_float(t));
        int cid = cell_of(ccv.x, ccv.y);
        g_cellid[i] = cid;
        atomicAdd(&g_ccnt[cid], 1);
        ccs = ccv.x * ccv.x + ccv.y * ccv.y;

        float ed = fabsf(tev - pev);
        float el = softclip_f(fmaf(10.0f, __expf(-0.1f * ed * ed), 0.01f * ed), 10.0f);
        float dx = tpv.x - ppv.x, dy = tpv.y - ppv.y;
        float pl = softclip_f(huber_f(sqrtf(fmaf(dx, dx, dy * dy) * 0.01f + 0.01f), 10.0f), 3.0f);
        float tl = softclip_f(huber_f(ttv - ptv, 2.0f), 6.0f);
        float s2 = pid0.x * pid0.x + pid0.y * pid0.y + pid1.x * pid1.x
                 + pid1.y * pid1.y + pid2.x * pid2.x + pid2.y * pid2.y;
        float cl = 1e-8f * (s2 * (1.0f / 6.0f));
        float payload = el + pl + tl + cl;
        float w = tev > 10.0f ? 1.0f : fmaxf((tev - 0.5f) * (1.0f / 9.5f), 0.0f);
        float pw = beta * w;

        if (t >= 0) {
            atomicAdd(&g_cnt[t], 1);
            unsigned long long key =
                (((unsigned long long)__float_as_uint(beta)) << 32) |
                (unsigned long long)(0xFFFFFFFFu - (unsigned)i);
            atomicMax(&g_amax[t], key);
            asm volatile("red.global.add.v2.f32 [%0], {%1, %2};"
                         :: "l"(&g_numden[t]), "f"(payload * pw), "f"(pw) : "memory");
        } else {
            ns = beta; ncnt = 1.0f;
        }
    }
    #pragma unroll
    for (int o = 16; o > 0; o >>= 1) {
        ns   += __shfl_down_sync(0xFFFFFFFF, ns, o);
        ncnt += __shfl_down_sync(0xFFFFFFFF, ncnt, o);
        ccs  += __shfl_down_sync(0xFFFFFFFF, ccs, o);
    }
    if ((threadIdx.x & 31) == 0) {
        if (ns != 0.0f || ncnt != 0.0f) { atomicAdd(&g_noise_sum, ns); atomicAdd(&g_noise_cnt, ncnt); }
        atomicAdd(&g_cc_sum, ccs);
    }

    // ---- last block: hit prefix-sum, alpha gather + counting sort ----
    __threadfence();
    if (threadIdx.x == 0) s_last = atomicAdd(&g_done_h, 1u);
    __syncthreads();
    if (s_last != gridDim.x - 1) return;

    __shared__ int s_ahist[NCELL];
    __shared__ int s_astart[NCELL];
    __shared__ int s_aoff[NCELL];
    if (threadIdx.x < NCELL) { s_ahist[threadIdx.x] = 0; s_aoff[threadIdx.x] = 0; }
    if (threadIdx.x == 0) {
        int acc = 0;
        for (int c = 0; c < NCELL; c++) { g_cstart[c] = acc; acc += g_ccnt[c]; }
        g_done_h = 0u;
    }
    __syncthreads();

    // gather 2 alphas per thread
    float ax[2], ay[2], aq[2]; int ac[2], akk[2];
    #pragma unroll
    for (int kk = 0; kk < 2; kk++) {
        int k = threadIdx.x + kk * 256;
        akk[kk] = k;
        if (g_cnt[k] > 0) {
            unsigned idx = 0xFFFFFFFFu - (unsigned)(g_amax[k] & 0xFFFFFFFFull);
            float b = clampb(pb[idx]);
            float lg = __logf(__fdividef(1.0f + b, 1.0f - b));
            float2 ccv = ((const float2*)cc)[idx];
            ax[kk] = ccv.x; ay[kk] = ccv.y; aq[kk] = fmaf(0.25f * lg, lg, 0.1f);
            g_alphaK[k] = make_float4(ccv.x, ccv.y, aq[kk], b);
        } else {
            ax[kk] = 0.f; ay[kk] = 0.f; aq[kk] = 0.f;
            g_alphaK[k] = make_float4(0.f, 0.f, 0.f, 1.f);
        }
        ac[kk] = cell_of(ax[kk], ay[kk]);
        atomicAdd(&s_ahist[ac[kk]], 1);
    }
    __syncthreads();
    if (threadIdx.x == 0) {
        int acc = 0;
        for (int c = 0; c < NCELL; c++) { s_astart[c] = acc; acc += s_ahist[c]; }
    }
    __syncthreads();
    #pragma unroll
    for (int kk = 0; kk < 2; kk++) {
        int pos = s_astart[ac[kk]] + atomicAdd(&s_aoff[ac[kk]], 1);
        g_alphaS[pos] = make_float4(ax[kk], ay[kk], aq[kk], __int_as_float(akk[kk]));
    }
}

// ---------------- kernel 1b: scatter hits into cell-sorted order ----------------
__global__ void __launch_bounds__(256) k_scatter() {
    int i = blockIdx.x * blockDim.x + threadIdx.x;
    if (i < NHIT) {
        int cid = g_cellid[i];
        int pos = g_cstart[cid] + atomicAdd(&g_coff[cid], 1);
        g_hit[pos] = g_tmp[i];
    } else if (i < NPAD) {
        g_hit[i] = make_float4(0.0f, 0.0f, 0.0f, __int_as_float(-1));  // q=0: inert
    }
}

// ---------------- kernel 2: pruned repulsion + O(N) att/correction + finalize ------
__global__ void __launch_bounds__(KHALF, 4) k_pairs(float* __restrict__ out) {
    __shared__ float4 sh[TILE];
    __shared__ float s_red[2 * KHALF];
    __shared__ float s_part[8][4];
    __shared__ float s_bbox[4];          // xmin, xmax, ymin, ymax
    __shared__ unsigned s_last;

    const int t = threadIdx.x;
    const int base = blockIdx.x * TILE;
    if (t < TILE) sh[t] = g_hit[base + t];
    __syncthreads();

    // ---- exact tile bbox ----
    {
        float mnx = 1e30f, mxx = -1e30f, mny = 1e30f, mxy = -1e30f;
        if (t < TILE) {
            float4 h = sh[t];
            mnx = h.x; mxx = h.x; mny = h.y; mxy = h.y;
        }
        #pragma unroll
        for (int o = 16; o > 0; o >>= 1) {
            mnx = fminf(mnx, __shfl_down_sync(0xFFFFFFFF, mnx, o));
            mxx = fmaxf(mxx, __shfl_down_sync(0xFFFFFFFF, mxx, o));
            mny = fminf(mny, __shfl_down_sync(0xFFFFFFFF, mny, o));
            mxy = fmaxf(mxy, __shfl_down_sync(0xFFFFFFFF, mxy, o));
        }
        int wid = t >> 5;
        if ((t & 31) == 0) {
            s_part[wid][0] = mnx; s_part[wid][1] = mxx;
            s_part[wid][2] = mny; s_part[wid][3] = mxy;
        }
        __syncthreads();
        if (t == 0) {
            float a = 1e30f, b = -1e30f, c = 1e30f, d = -1e30f;
            #pragma unroll
            for (int wv = 0; wv < 4; wv++) {    // warps 0-3 hold the 128 hits
                a = fminf(a, s_part[wv][0]); b = fmaxf(b, s_part[wv][1]);
                c = fminf(c, s_part[wv][2]); d = fmaxf(d, s_part[wv][3]);
            }
            s_bbox[0] = a; s_bbox[1] = b; s_bbox[2] = c; s_bbox[3] = d;
        }
        __syncthreads();
    }
    const float bxmin = s_bbox[0], bxmax = s_bbox[1];
    const float bymin = s_bbox[2], bymax = s_bbox[3];

    // ---- per-object pruned repulsion loops (2 sorted objects per thread) ----
    #pragma unroll
    for (int o = 0; o < 2; o++) {
        float4 s = g_alphaS[t + o * KHALF];
        float ddx = fmaxf(fmaxf(bxmin - s.x, s.x - bxmax), 0.0f);
        float ddy = fmaxf(fmaxf(bymin - s.y, s.y - bymax), 0.0f);
        if (s.z > 0.0f && fmaf(ddx, ddx, ddy * ddy) < 1.0f) {
            float rep = 0.0f;
            #pragma unroll 1
            for (int j = 0; j < TILE; j += 8) {
                float4 h0 = sh[j + 0], h1 = sh[j + 1], h2 = sh[j + 2], h3 = sh[j + 3];
                float4 h4 = sh[j + 4], h5 = sh[j + 5], h6 = sh[j + 6], h7 = sh[j + 7];
                PAIR1(h0, s.x, s.y, rep) PAIR1(h1, s.x, s.y, rep)
                PAIR1(h2, s.x, s.y, rep) PAIR1(h3, s.x, s.y, rep)
                PAIR1(h4, s.x, s.y, rep) PAIR1(h5, s.x, s.y, rep)
                PAIR1(h6, s.x, s.y, rep) PAIR1(h7, s.x, s.y, rep)
            }
            atomicAdd(&g_rep[__float_as_int(s.w)], rep * s.z);
        }
    }

    // ---- O(N) attraction + member-repulsion correction ----
    if (t < TILE) {
        float4 h = sh[t];
        int ti = __float_as_int(h.w);
        if (ti >= 0) {
            float4 a = g_alphaK[ti];
            float dx = h.x - a.x, dy = h.y - a.y;
            float d2e = fmaf(dx, dx, fmaf(dy, dy, 1e-6f));
            float d2  = fmaf(dx, dx, dy * dy);
            float r = __saturatef(1.0f - sqapx(d2e));
            atomicAdd(&g_att[ti],  d2 * h.z * a.z);
            atomicAdd(&g_rep[ti], -r  * h.z * a.z);
        }
    }

    // ---- last block finalizes + resets all scratch for next graph replay ----
    __threadfence();
    if (t == 0) s_last = atomicAdd(&g_done_p, 1u);
    __syncthreads();
    if (s_last != gridDim.x - 1) return;

    float obj = 0.f, has = 0.f;
    #pragma unroll
    for (int kk = 0; kk < 2; kk++) {
        int k = t + kk * KHALF;
        int c = g_cnt[k];
        if (c > 0) {
            has += 1.0f;
            float fc = (float)c;
            float2 nd = g_numden[k];
            obj += g_att[k] / (fc + 1e-9f)
                 + g_rep[k] / ((float)NHIT - fc + 1e-9f)
                 + nd.x / (nd.y + 1e-9f)
                 + (1.0f - g_alphaK[k].w);
        }
        g_amax[k] = 0ull; g_cnt[k] = 0;
        g_numden[k] = make_float2(0.f, 0.f); g_att[k] = 0.f; g_rep[k] = 0.f;
    }
    if (t < NCELL) { g_ccnt[t] = 0; g_coff[t] = 0; }
    s_red[t] = obj; s_red[t + KHALF] = has;
    __syncthreads();
    #pragma unroll
    for (int o = KHALF / 2; o > 0; o >>= 1) {
        if (t < o) { s_red[t] += s_red[t + o]; s_red[t + KHALF] += s_red[t + KHALF + o]; }
        __syncthreads();
    }
    if (t == 0) {
        float n_obj = s_red[KHALF] + 1e-9f;
        float total = s_red[0] / n_obj
                    + g_noise_sum / (g_noise_cnt + 1e-9f)
                    + 0.001f * g_cc_sum * (1.0f / (float)(NHIT * 2));
        out[0] = total;
        g_noise_sum = 0.f; g_noise_cnt = 0.f; g_cc_sum = 0.f; g_done_p = 0u;
    }
}

// ---------------- launch ----------------
extern "C" void kernel_launch(void* const* d_in, const int* in_sizes, int n_in,
                              void* d_out, int out_size) {
    const float* pb  = (const float*)d_in[0];
    const float* cc  = (const float*)d_in[1];
    const float* pe  = (const float*)d_in[2];
    const float* pp  = (const float*)d_in[3];
    const float* pt  = (const float*)d_in[4];
    const float* pid = (const float*)d_in[5];
    const int*   tix = (const int*)  d_in[6];
    const float* te  = (const float*)d_in[7];
    const float* tp  = (const float*)d_in[8];
    const float* tt  = (const float*)d_in[9];

    k_hits<<<HBLK, 256>>>(pb, cc, pe, pp, pt, pid, tix, te, tp, tt);
    k_scatter<<<NPAD / 256, 256>>>();
    k_pairs<<<NBLK, KHALF>>>((float*)d_out);
}

// round 11
// speedup vs baseline: 2.0740x; 2.0740x over previous
#include <cuda_runtime.h>
#include <math.h>

#define NHIT 80000
#define KOBJ 512
#define HBLK 313               // 313*256 = 80128 threads, covers NHIT
#define EPSF 1e-9f

// ---------------- scratch (device globals; zero at load, reset after use) ----------
__device__ float4 g_hit[NHIT];                 // x, y, q, t_idx (int bits)
__device__ float4 g_A[KOBJ];                   // x_a, y_a, q_a/(N-cnt), q_a/cnt
__device__ float  g_beta_a[KOBJ];              // beta at condensation point
__device__ unsigned long long g_amax[KOBJ];    // packed (beta_bits<<32 | ~idx)
__device__ int    g_cnt[KOBJ];
__device__ float2 g_numden[KOBJ];              // payload num, den
__device__ float  g_pairsum;                   // flattened att+rep (x n_obj)
__device__ float  g_noise_sum, g_noise_cnt, g_cc_sum;
__device__ unsigned g_done_h, g_done_p;

__device__ __forceinline__ float clampb(float b) {
    return fminf(fmaxf(b, 1e-6f), 1.0f - 1e-6f);
}
__device__ __forceinline__ float softclip_f(float x, float c) {
    x = x * (1.0f / c);
    if (x > 1.0f) x = __logf(x + 1.0f);
    return x * c;
}
__device__ __forceinline__ float huber_f(float x, float d) {
    float ax = fabsf(x);
    return ax < d ? x * x : d * d + 2.0f * d * (ax - d);
}
__device__ __forceinline__ float sqapx(float x) {
    float s; asm("sqrt.approx.f32 %0, %1;" : "=f"(s) : "f"(x)); return s;
}

// acc += sat(1 - sqrt(d2)) * Q     (fused hinge-accumulate)
#define REP_ACC(D2, Q, ACC)                                         \
    asm("{ .reg .f32 s;\n\t"                                        \
        " sqrt.approx.f32 s, %1;\n\t"                               \
        " sub.rn.sat.f32 s, 0f3F800000, s;\n\t"                     \
        " fma.rn.f32 %0, s, %2, %0;\n\t}"                           \
        : "+f"(ACC) : "f"(D2), "f"(Q));

// one k step: hit (hx,hy) vs staged alpha a
#define KSTEP(A)                                                    \
    {                                                               \
        float dx = hx - (A).x, dy = hy - (A).y;                     \
        float d2 = fmaf(dx, dx, fmaf(dy, dy, 1e-6f));               \
        REP_ACC(d2, (A).z, acc)                                     \
    }

// ---------------- kernel 1: per-hit pass + fused alpha/A-table build ----------------
__global__ void __launch_bounds__(256) k_hits(
        const float* __restrict__ pb,  const float* __restrict__ cc,
        const float* __restrict__ pe,  const float* __restrict__ pp,
        const float* __restrict__ pt,  const float* __restrict__ pid,
        const int*   __restrict__ tix, const float* __restrict__ te,
        const float* __restrict__ tp,  const float* __restrict__ tt) {
    __shared__ unsigned s_last;
    int i = blockIdx.x * blockDim.x + threadIdx.x;
    float ns = 0.0f, ncnt = 0.0f, ccs = 0.0f;
    if (i < NHIT) {   // warp-uniform (80000 % 32 == 0)
        float  braw = pb[i];
        int    t    = tix[i];
        float2 ccv  = ((const float2*)cc)[i];
        float  pev  = pe[i];
        float2 ppv  = ((const float2*)pp)[i];
        float  ptv  = pt[i];
        float  tev  = te[i];
        float2 tpv  = ((const float2*)tp)[i];
        float  ttv  = tt[i];
        float2 pid0 = ((const float2*)pid)[3 * i];
        float2 pid1 = ((const float2*)pid)[3 * i + 1];
        float2 pid2 = ((const float2*)pid)[3 * i + 2];

        float beta = clampb(braw);
        float lg = __logf(__fdividef(1.0f + beta, 1.0f - beta));
        float q = fmaf(0.25f * lg, lg, 0.1f);
        g_hit[i] = make_float4(ccv.x, ccv.y, q, __int_as_float(t));
        ccs = ccv.x * ccv.x + ccv.y * ccv.y;

        float ed = fabsf(tev - pev);
        float el = softclip_f(fmaf(10.0f, __expf(-0.1f * ed * ed), 0.01f * ed), 10.0f);
        float dx = tpv.x - ppv.x, dy = tpv.y - ppv.y;
        float pl = softclip_f(huber_f(sqrtf(fmaf(dx, dx, dy * dy) * 0.01f + 0.01f), 10.0f), 3.0f);
        float tl = softclip_f(huber_f(ttv - ptv, 2.0f), 6.0f);
        float s2 = pid0.x * pid0.x + pid0.y * pid0.y + pid1.x * pid1.x
                 + pid1.y * pid1.y + pid2.x * pid2.x + pid2.y * pid2.y;
        float cl = 1e-8f * (s2 * (1.0f / 6.0f));
        float payload = el + pl + tl + cl;
        float w = tev > 10.0f ? 1.0f : fmaxf((tev - 0.5f) * (1.0f / 9.5f), 0.0f);
        float pw = beta * w;

        if (t >= 0) {
            atomicAdd(&g_cnt[t], 1);
            unsigned long long key =
                (((unsigned long long)__float_as_uint(beta)) << 32) |
                (unsigned long long)(0xFFFFFFFFu - (unsigned)i);
            atomicMax(&g_amax[t], key);
            asm volatile("red.global.add.v2.f32 [%0], {%1, %2};"
                         :: "l"(&g_numden[t]), "f"(payload * pw), "f"(pw) : "memory");
        } else {
            ns = beta; ncnt = 1.0f;
        }
    }
    #pragma unroll
    for (int o = 16; o > 0; o >>= 1) {
        ns   += __shfl_down_sync(0xFFFFFFFF, ns, o);
        ncnt += __shfl_down_sync(0xFFFFFFFF, ncnt, o);
        ccs  += __shfl_down_sync(0xFFFFFFFF, ccs, o);
    }
    if ((threadIdx.x & 31) == 0) {
        if (ns != 0.0f || ncnt != 0.0f) { atomicAdd(&g_noise_sum, ns); atomicAdd(&g_noise_cnt, ncnt); }
        atomicAdd(&g_cc_sum, ccs);
    }

    // ---- last block builds the A-table (folded normalizers) ----
    __threadfence();
    if (threadIdx.x == 0) s_last = atomicAdd(&g_done_h, 1u);
    __syncthreads();
    if (s_last != gridDim.x - 1) return;

    #pragma unroll
    for (int kk = 0; kk < 2; kk++) {
        int k = threadIdx.x + kk * 256;
        int c = g_cnt[k];
        if (c > 0) {
            unsigned idx = 0xFFFFFFFFu - (unsigned)(g_amax[k] & 0xFFFFFFFFull);
            float b = clampb(pb[idx]);
            float lg = __logf(__fdividef(1.0f + b, 1.0f - b));
            float qa = fmaf(0.25f * lg, lg, 0.1f);
            float2 ccv = ((const float2*)cc)[idx];
            float fc = (float)c;
            g_A[k] = make_float4(ccv.x, ccv.y,
                                 qa / ((float)NHIT - fc + EPSF),   // repulsion weight
                                 qa / (fc + EPSF));                // attraction weight
            g_beta_a[k] = b;
        } else {
            g_A[k] = make_float4(0.f, 0.f, 0.f, 0.f);   // inert: contributes 0
            g_beta_a[k] = 1.0f;
        }
    }
    if (threadIdx.x == 0) g_done_h = 0u;   // reset for next graph replay
}

// ---------------- kernel 2: hit-parallel flattened N x K + finalize ----------------
__global__ void __launch_bounds__(256, 4) k_rep(float* __restrict__ out) {
    __shared__ float4 sA[KOBJ];          // 8KB: all condensation points
    __shared__ float s_red[512];
    __shared__ unsigned s_last;

    const int t = threadIdx.x;
    sA[t]       = g_A[t];
    sA[t + 256] = g_A[t + 256];
    __syncthreads();

    const int i = blockIdx.x * blockDim.x + t;
    float contrib = 0.0f;
    if (i < NHIT) {    // warp-uniform
        float4 h = g_hit[i];
        const float hx = h.x, hy = h.y;
        float acc = 0.0f;

        #pragma unroll 4
        for (int k = 0; k < KOBJ; k++) {
            float4 a = sA[k];            // uniform k -> broadcast LDS.128
            KSTEP(a)
        }

        // member terms: remove own-object repulsion, add attraction
        int ti = __float_as_int(h.w);
        if (ti >= 0) {
            float4 a = sA[ti];
            float dx = hx - a.x, dy = hy - a.y;
            float d2e = fmaf(dx, dx, fmaf(dy, dy, 1e-6f));
            float d2  = fmaf(dx, dx, dy * dy);        // reference att: no eps
            float r = __saturatef(1.0f - sqapx(d2e)); // same formula as loop -> cancels
            acc = fmaf(-r, a.z, acc);
            acc = fmaf(d2, a.w, acc);
        }
        contrib = h.z * acc;
    }
    #pragma unroll
    for (int o = 16; o > 0; o >>= 1)
        contrib += __shfl_down_sync(0xFFFFFFFF, contrib, o);
    if ((t & 31) == 0) atomicAdd(&g_pairsum, contrib);

    // ---- last block finalizes + resets scratch for next graph replay ----
    __threadfence();
    if (t == 0) s_last = atomicAdd(&g_done_p, 1u);
    __syncthreads();
    if (s_last != gridDim.x - 1) return;

    float obj = 0.f, has = 0.f;
    #pragma unroll
    for (int kk = 0; kk < 2; kk++) {
        int k = t + kk * 256;
        int c = g_cnt[k];
        if (c > 0) {
            has += 1.0f;
            float2 nd = g_numden[k];
            obj += nd.x / (nd.y + EPSF) + (1.0f - g_beta_a[k]);
        }
        g_amax[k] = 0ull; g_cnt[k] = 0;
        g_numden[k] = make_float2(0.f, 0.f);
    }
    s_red[t] = obj; s_red[t + 256] = has;
    __syncthreads();
    #pragma unroll
    for (int o = 128; o > 0; o >>= 1) {
        if (t < o) { s_red[t] += s_red[t + o]; s_red[t + 256] += s_red[t + 256 + o]; }
        __syncthreads();
    }
    if (t == 0) {
        float n_obj = s_red[256] + EPSF;
        float total = (s_red[0] + g_pairsum) / n_obj
                    + g_noise_sum / (g_noise_cnt + EPSF)
                    + 0.001f * g_cc_sum * (1.0f / (float)(NHIT * 2));
        out[0] = total;
        g_pairsum = 0.f; g_noise_sum = 0.f; g_noise_cnt = 0.f; g_cc_sum = 0.f;
        g_done_p = 0u;
    }
}

// ---------------- launch ----------------
extern "C" void kernel_launch(void* const* d_in, const int* in_sizes, int n_in,
                              void* d_out, int out_size) {
    const float* pb  = (const float*)d_in[0];
    const float* cc  = (const float*)d_in[1];
    const float* pe  = (const float*)d_in[2];
    const float* pp  = (const float*)d_in[3];
    const float* pt  = (const float*)d_in[4];
    const float* pid = (const float*)d_in[5];
    const int*   tix = (const int*)  d_in[6];
    const float* te  = (const float*)d_in[7];
    const float* tp  = (const float*)d_in[8];
    const float* tt  = (const float*)d_in[9];

    k_hits<<<HBLK, 256>>>(pb, cc, pe, pp, pt, pid, tix, te, tp, tt);
    k_rep<<<HBLK, 256>>>((float*)d_out);
}